// round 14
// baseline (speedup 1.0000x reference)
#include <cuda_runtime.h>
#include <stdint.h>

#define NSITES   144
#define NHID     256
#define G3       768
#define BATCH    1024
#define NB       8
#define NBLOCKS  (BATCH / NB)
#define THREADS  768
#define NQ       4
#define KQ       (NHID / NQ)       // 64 k-iters per thread
#define NCG      192               // col-groups of 4 consecutive columns
#define HSTRIDE  12                // h_s row stride (floats): 48B rows, 16B-aligned

// dynamic smem layout (bytes)
#define RED_OFF  0
#define RED_SZ   (NQ * NCG * 16 * 8)                  // 98304: red[q][cg][16] u64
#define H_OFF    (RED_OFF + RED_SZ)
#define H_SZ     (NHID * HSTRIDE * 4)                 // 12288
#define GX_OFF   (H_OFF + H_SZ)
#define GX_SZ    (3 * G3 * 4)                         // 9216
#define GUM_OFF  (GX_OFF + GX_SZ)
#define GUM_SZ   (NSITES * NB * 2 * 4)                // 9216
#define S_OFF    (GUM_OFF + GUM_SZ)
#define SMEM_TOTAL (S_OFF + 64)                       // ~129 KB

// ---------------- threefry2x32 core (JAX schedule) ----------------
__device__ __forceinline__ uint32_t rotl32(uint32_t x, uint32_t r) {
    return __funnelshift_l(x, x, r);
}

__device__ __forceinline__ void tf2x32(uint32_t k0, uint32_t k1,
                                       uint32_t x0, uint32_t x1,
                                       uint32_t &o0, uint32_t &o1) {
    uint32_t k2 = k0 ^ k1 ^ 0x1BD11BDAu;
    x0 += k0; x1 += k1;
#define TFR(r) { x0 += x1; x1 = rotl32(x1, r); x1 ^= x0; }
    TFR(13) TFR(15) TFR(26) TFR(6)    x0 += k1; x1 += k2 + 1u;
    TFR(17) TFR(29) TFR(16) TFR(24)   x0 += k2; x1 += k0 + 2u;
    TFR(13) TFR(15) TFR(26) TFR(6)    x0 += k0; x1 += k1 + 3u;
    TFR(17) TFR(29) TFR(16) TFR(24)   x0 += k1; x1 += k2 + 4u;
    TFR(13) TFR(15) TFR(26) TFR(6)    x0 += k2; x1 += k0 + 5u;
#undef TFR
    o0 = x0; o1 = x1;
}

// Partitionable random_bits (32-bit): element i = w0 ^ w1 of tf2x32(key, (0, i))
__device__ __forceinline__ uint32_t rbits_part(uint32_t k0, uint32_t k1, uint32_t i) {
    uint32_t o0, o1;
    tf2x32(k0, k1, 0u, i, o0, o1);
    return o0 ^ o1;
}

// jax.random.gumbel: -log(-log(uniform(tiny, 1)))
__device__ __forceinline__ float gumbel_from(uint32_t bits) {
    const float TINY = 1.17549435e-38f;
    float f = __uint_as_float((bits >> 9) | 0x3f800000u) - 1.0f;
    float u = fmaxf(TINY, f + TINY);
    return -logf(-logf(u));
}

// ---------------- packed f32x2 ops (sm_100+) ----------------
__device__ __forceinline__ void fma2(unsigned long long &d, unsigned long long a,
                                     unsigned long long b) {
    asm("fma.rn.f32x2 %0, %1, %2, %0;" : "+l"(d) : "l"(a), "l"(b));
}
__device__ __forceinline__ unsigned long long pack2(float x) {
    unsigned long long r;
    asm("mov.b64 %0, {%1, %1};" : "=l"(r) : "f"(x));
    return r;
}
__device__ __forceinline__ unsigned long long add2(unsigned long long a,
                                                   unsigned long long b) {
    unsigned long long r;
    asm("add.rn.f32x2 %0, %1, %2;" : "=l"(r) : "l"(a), "l"(b));
    return r;
}
__device__ __forceinline__ void unpack2(unsigned long long v, float &lo, float &hi) {
    asm("mov.b64 {%0, %1}, %2;" : "=f"(lo), "=f"(hi) : "l"(v));
}

__device__ __forceinline__ float sigmoid_x(float x) {
    return 0.5f + 0.5f * tanhf(0.5f * x);
}

__global__ void __launch_bounds__(THREADS, 1)
rnn_sample_kernel(const float* __restrict__ Wx,    // kernel      [2, 768]
                  const float* __restrict__ Wh,    // rec_kernel  [256, 768]
                  const float* __restrict__ bias,  // [2, 768]
                  const float* __restrict__ Dw,    // dense_w     [256, 2]
                  const float* __restrict__ Db,    // dense_b     [2]
                  float* __restrict__ out)         // samples [1024,144] then logP [1024]
{
    extern __shared__ __align__(16) char smem_raw[];
    unsigned long long* red = reinterpret_cast<unsigned long long*>(smem_raw + RED_OFF);
    float* h_s  = reinterpret_cast<float*>(smem_raw + H_OFF);   // [k][b], stride 12
    float* gx_s = reinterpret_cast<float*>(smem_raw + GX_OFF);  // [x-case][col]
    float* gum  = reinterpret_cast<float*>(smem_raw + GUM_OFF); // [t][b][cls]
    int*   s_arr = reinterpret_cast<int*>(smem_raw + S_OFF);

    const int tid  = threadIdx.x;
    const int lane = tid & 31;
    const int warp = tid >> 5;
    const int q    = tid / NCG;      // k-quarter (warps 0-5 -> q0, ... no straddle)
    const int cg   = tid - q * NCG;  // col-group: cols 4cg..4cg+3 of the 768-col gates
    const int bbase = blockIdx.x * NB;

    // phase-2 identity (threads 0..511): gate unit j, sample-half
    const int j2   = tid & 255;
    const int hf   = tid >> 8;       // 0 or 1 (only meaningful for tid < 512)

    // ---- one-time init ----
    for (int i = tid; i < NHID * HSTRIDE; i += THREADS) h_s[i] = 0.0f;
    for (int c = tid; c < G3; c += THREADS) {
        float b0 = bias[c];
        gx_s[c]          = b0;              // x = 0 (t=0)
        gx_s[G3 + c]     = Wx[c] + b0;      // one_hot(0)
        gx_s[2 * G3 + c] = Wx[G3 + c] + b0; // one_hot(1)
    }
    for (int i = tid; i < NSITES * NB * 2; i += THREADS) {
        int t = i >> 4, r = i & 15;
        int b = r >> 1, cls = r & 1;
        uint32_t o0, o1;
        tf2x32(0u, 42u, 0u, (uint32_t)t, o0, o1);       // partitionable split -> step key
        gum[i] = gumbel_from(rbits_part(o0, o1, (uint32_t)(2 * (bbase + b) + cls)));
    }
    if (tid < NB) s_arr[tid] = -1;
    float logP = 0.0f;   // lane 0 of warps 0..7 (sample = warp id)
    __syncthreads();

    const float b1z = bias[G3 + j2], b1r = bias[G3 + 256 + j2], b1n = bias[G3 + 512 + j2];
    const float db0 = Db[0], db1 = Db[1];
    const int k0 = q * KQ;
    const float4* wbase =
        reinterpret_cast<const float4*>(Wh + k0 * G3 + 4 * cg);   // stride G3/4 float4
    const float* hbase0 = h_s + k0 * HSTRIDE;
    unsigned long long* myred = red + (q * NCG + cg) * 16;

    for (int i = 0; i < NSITES; ++i) {
        // ======== phase 1: k-loop, 4 cols x 8 samples over my k-quarter ========
        unsigned long long acc[16];   // [c][pair]: c=col-in-group, pair=(2b,2b+1)
#pragma unroll
        for (int a = 0; a < 16; ++a) acc[a] = 0ull;
        const float4* wp = wbase;
#pragma unroll 4
        for (int k = 0; k < KQ; ++k) {
            float4 w4 = *wp; wp += G3 / 4;
            const ulonglong2* hp =
                reinterpret_cast<const ulonglong2*>(hbase0 + k * HSTRIDE);
            ulonglong2 hA = hp[0], hB = hp[1];
            unsigned long long wq;
            wq = pack2(w4.x);
            fma2(acc[0], wq, hA.x); fma2(acc[1], wq, hA.y);
            fma2(acc[2], wq, hB.x); fma2(acc[3], wq, hB.y);
            wq = pack2(w4.y);
            fma2(acc[4], wq, hA.x); fma2(acc[5], wq, hA.y);
            fma2(acc[6], wq, hB.x); fma2(acc[7], wq, hB.y);
            wq = pack2(w4.z);
            fma2(acc[8], wq, hA.x); fma2(acc[9], wq, hA.y);
            fma2(acc[10], wq, hB.x); fma2(acc[11], wq, hB.y);
            wq = pack2(w4.w);
            fma2(acc[12], wq, hA.x); fma2(acc[13], wq, hA.y);
            fma2(acc[14], wq, hB.x); fma2(acc[15], wq, hB.y);
        }
        // publish all 16 partials: red[q][cg][c*4+p]
#pragma unroll
        for (int s = 0; s < 16; ++s) myred[s] = acc[s];

        // head for step i-1 (warps 0-7; h_s stable during phase 1)
        if (warp < NB && i > 0) {
            const int b = warp, t = i - 1;
            float c0 = 0.0f, c1 = 0.0f;
            for (int k = lane; k < NHID; k += 32) {
                float hv = h_s[k * HSTRIDE + b];
                c0 += hv * Dw[2 * k];
                c1 += hv * Dw[2 * k + 1];
            }
#pragma unroll
            for (int off = 16; off > 0; off >>= 1) {
                c0 += __shfl_down_sync(0xffffffffu, c0, off);
                c1 += __shfl_down_sync(0xffffffffu, c1, off);
            }
            if (lane == 0) {
                float la = c0 + db0, lb = c1 + db1;
                float m  = fmaxf(la, lb);
                float ea = expf(la - m), eb = expf(lb - m);
                float sm = ea + eb;
                float lp0 = logf(1e-10f + ea / sm);
                float lp1 = logf(1e-10f + eb / sm);
                float g0 = gum[(t * NB + b) * 2];
                float g1 = gum[(t * NB + b) * 2 + 1];
                int s = (g1 + lp1 > g0 + lp0) ? 1 : 0;   // argmax ties -> index 0
                logP += s ? lp1 : lp0;
                s_arr[b] = s;
                out[(bbase + b) * NSITES + t] = (float)s;
            }
        }
        __syncthreads();   // red ready; s_arr ready; all h reads done

        // ======== phase 2 (tid<512): combine quarters + gates for (j2, hf) ========
        if (tid < 512) {
            // gate g column = g*256 + j2 -> cg_g = (g*256+j2)>>2 = g*64 + (j2>>2)
            const int ci = j2 & 3;                      // col within group
            const int cgz = (j2 >> 2),  cgr = 64 + cgz, cgn = 128 + cgz;
            const int p0 = 2 * hf, p1 = 2 * hf + 1;     // my sample pairs
            unsigned long long sz0, sz1, sr0, sr1, sn0, sn1;
            {
                const unsigned long long* rz = red + cgz * 16 + ci * 4;
                const unsigned long long* rr = red + cgr * 16 + ci * 4;
                const unsigned long long* rn = red + cgn * 16 + ci * 4;
                sz0 = rz[p0]; sz1 = rz[p1];
                sr0 = rr[p0]; sr1 = rr[p1];
                sn0 = rn[p0]; sn1 = rn[p1];
#pragma unroll
                for (int src = 1; src < NQ; ++src) {
                    const int o = src * NCG * 16;
                    sz0 = add2(sz0, rz[o + p0]); sz1 = add2(sz1, rz[o + p1]);
                    sr0 = add2(sr0, rr[o + p0]); sr1 = add2(sr1, rr[o + p1]);
                    sn0 = add2(sn0, rn[o + p0]); sn1 = add2(sn1, rn[o + p1]);
                }
            }
            float gz[4], gr[4], gn[4];
            unpack2(sz0, gz[0], gz[1]); unpack2(sz1, gz[2], gz[3]);
            unpack2(sr0, gr[0], gr[1]); unpack2(sr1, gr[2], gr[3]);
            unpack2(sn0, gn[0], gn[1]); unpack2(sn1, gn[2], gn[3]);

            float4 hold = *reinterpret_cast<float4*>(h_s + j2 * HSTRIDE + 4 * hf);
            float ho[4] = {hold.x, hold.y, hold.z, hold.w};
            float hn4[4];
#pragma unroll
            for (int v = 0; v < 4; ++v) {
                int b = 4 * hf + v;
                int idx = s_arr[b] + 1;                 // -1 -> 0 (x = 0 at t=0)
                float gxz = gx_s[idx * G3 + j2];
                float gxr = gx_s[idx * G3 + 256 + j2];
                float gxn = gx_s[idx * G3 + 512 + j2];
                float z  = sigmoid_x(gxz + gz[v] + b1z);
                float r  = sigmoid_x(gxr + gr[v] + b1r);
                float hh = tanhf(gxn + r * (gn[v] + b1n));
                hn4[v] = z * ho[v] + (1.0f - z) * hh;
            }
            *reinterpret_cast<float4*>(h_s + j2 * HSTRIDE + 4 * hf) =
                make_float4(hn4[0], hn4[1], hn4[2], hn4[3]);
        }
        __syncthreads();   // h ready for next k-loop / head
    }

    // ======== epilogue head: step NSITES-1 from final h ========
    if (warp < NB) {
        const int b = warp, t = NSITES - 1;
        float c0 = 0.0f, c1 = 0.0f;
        for (int k = lane; k < NHID; k += 32) {
            float hv = h_s[k * HSTRIDE + b];
            c0 += hv * Dw[2 * k];
            c1 += hv * Dw[2 * k + 1];
        }
#pragma unroll
        for (int off = 16; off > 0; off >>= 1) {
            c0 += __shfl_down_sync(0xffffffffu, c0, off);
            c1 += __shfl_down_sync(0xffffffffu, c1, off);
        }
        if (lane == 0) {
            float la = c0 + db0, lb = c1 + db1;
            float m  = fmaxf(la, lb);
            float ea = expf(la - m), eb = expf(lb - m);
            float sm = ea + eb;
            float lp0 = logf(1e-10f + ea / sm);
            float lp1 = logf(1e-10f + eb / sm);
            float g0 = gum[(t * NB + b) * 2];
            float g1 = gum[(t * NB + b) * 2 + 1];
            int s = (g1 + lp1 > g0 + lp0) ? 1 : 0;
            logP += s ? lp1 : lp0;
            out[(bbase + b) * NSITES + t] = (float)s;
            out[BATCH * NSITES + bbase + b] = logP;
        }
    }
}

extern "C" void kernel_launch(void* const* d_in, const int* in_sizes, int n_in,
                              void* d_out, int out_size) {
    (void)in_sizes; (void)n_in; (void)out_size;
    const float* Wx   = (const float*)d_in[0];
    const float* Wh   = (const float*)d_in[1];
    const float* bias = (const float*)d_in[2];
    const float* Dw   = (const float*)d_in[3];
    const float* Db   = (const float*)d_in[4];
    float* out = (float*)d_out;
    cudaFuncSetAttribute(rnn_sample_kernel,
                         cudaFuncAttributeMaxDynamicSharedMemorySize, SMEM_TOTAL);
    rnn_sample_kernel<<<NBLOCKS, THREADS, SMEM_TOTAL>>>(Wx, Wh, bias, Dw, Db, out);
}

// round 16
// speedup vs baseline: 1.2867x; 1.2867x over previous
#include <cuda_runtime.h>
#include <stdint.h>

#define NSITES   144
#define NHID     256
#define G3       768
#define BATCH    1024
#define NB       8
#define NBLOCKS  128
#define THREADS  544               // 16 consumer warps + 1 producer warp
#define HSTRIDE  12
#define CHUNK_K  16
#define NCHUNK   16                // chunks per step (16 x 16 = 256 k)
#define RING     3
#define CHUNK_BYTES (CHUNK_K * G3 * 4)   // 49152
#define SLICE_BYTES (CHUNK_BYTES / 2)    // 24576 per rank

// dynamic smem layout (bytes)
#define W_OFF    0
#define H_OFF    (RING * CHUNK_BYTES)            // 147456
#define RED_OFF  (H_OFF + NHID * HSTRIDE * 4)    // 159744
#define GUM_OFF  (RED_OFF + 6 * 2 * NHID * 8)    // 184320
#define S_OFF    (GUM_OFF + NSITES * NB * 2 * 4) // 193536
#define MB_OFF   (S_OFF + 64)                    // 193600: full[3] then empty[3]
#define SMEM_TOTAL (MB_OFF + 64)                 // 193664

// ---------------- threefry2x32 (JAX partitionable) ----------------
__device__ __forceinline__ uint32_t rotl32(uint32_t x, uint32_t r) {
    return __funnelshift_l(x, x, r);
}
__device__ __forceinline__ void tf2x32(uint32_t k0, uint32_t k1,
                                       uint32_t x0, uint32_t x1,
                                       uint32_t &o0, uint32_t &o1) {
    uint32_t k2 = k0 ^ k1 ^ 0x1BD11BDAu;
    x0 += k0; x1 += k1;
#define TFR(r) { x0 += x1; x1 = rotl32(x1, r); x1 ^= x0; }
    TFR(13) TFR(15) TFR(26) TFR(6)    x0 += k1; x1 += k2 + 1u;
    TFR(17) TFR(29) TFR(16) TFR(24)   x0 += k2; x1 += k0 + 2u;
    TFR(13) TFR(15) TFR(26) TFR(6)    x0 += k0; x1 += k1 + 3u;
    TFR(17) TFR(29) TFR(16) TFR(24)   x0 += k1; x1 += k2 + 4u;
    TFR(13) TFR(15) TFR(26) TFR(6)    x0 += k2; x1 += k0 + 5u;
#undef TFR
    o0 = x0; o1 = x1;
}
__device__ __forceinline__ uint32_t rbits_part(uint32_t k0, uint32_t k1, uint32_t i) {
    uint32_t o0, o1;
    tf2x32(k0, k1, 0u, i, o0, o1);
    return o0 ^ o1;
}
__device__ __forceinline__ float gumbel_from(uint32_t bits) {
    const float TINY = 1.17549435e-38f;
    float f = __uint_as_float((bits >> 9) | 0x3f800000u) - 1.0f;
    float u = fmaxf(TINY, f + TINY);
    return -logf(-logf(u));
}

// ---------------- packed f32x2 ----------------
__device__ __forceinline__ void fma2(unsigned long long &d, unsigned long long a,
                                     unsigned long long b) {
    asm("fma.rn.f32x2 %0, %1, %2, %0;" : "+l"(d) : "l"(a), "l"(b));
}
__device__ __forceinline__ unsigned long long pack2(float x) {
    unsigned long long r;
    asm("mov.b64 %0, {%1, %1};" : "=l"(r) : "f"(x));
    return r;
}
__device__ __forceinline__ unsigned long long add2(unsigned long long a,
                                                   unsigned long long b) {
    unsigned long long r;
    asm("add.rn.f32x2 %0, %1, %2;" : "=l"(r) : "l"(a), "l"(b));
    return r;
}
__device__ __forceinline__ void unpack2(unsigned long long v, float &lo, float &hi) {
    asm("mov.b64 {%0, %1}, %2;" : "=f"(lo), "=f"(hi) : "l"(v));
}
__device__ __forceinline__ float sigmoid_x(float x) {
    return 0.5f + 0.5f * tanhf(0.5f * x);
}

// ---------------- cluster / mbarrier / TMA helpers ----------------
__device__ __forceinline__ uint32_t smem_u32(const void* p) {
    uint32_t a;
    asm("{ .reg .u64 t; cvta.to.shared.u64 t, %1; cvt.u32.u64 %0, t; }"
        : "=r"(a) : "l"(p));
    return a;
}
__device__ __forceinline__ uint32_t ctarank() {
    uint32_t r; asm("mov.u32 %0, %%cluster_ctarank;" : "=r"(r)); return r;
}
__device__ __forceinline__ void mbar_init(uint32_t m, uint32_t cnt) {
    asm volatile("mbarrier.init.shared.b64 [%0], %1;" :: "r"(m), "r"(cnt) : "memory");
}
__device__ __forceinline__ void mbar_wait(uint32_t m, uint32_t parity) {
    asm volatile(
        "{\n\t.reg .pred P;\n"
        "LW_%=:\n\t"
        "mbarrier.try_wait.parity.shared::cta.b64 P, [%0], %1, 0x989680;\n\t"
        "@!P bra LW_%=;\n\t}"
        :: "r"(m), "r"(parity) : "memory");
}
__device__ __forceinline__ void mbar_arrive(uint32_t m) {
    asm volatile("mbarrier.arrive.shared::cta.b64 _, [%0];" :: "r"(m) : "memory");
}
__device__ __forceinline__ void mbar_arrive_peer(uint32_t m, uint32_t peer) {
    asm volatile(
        "{\n\t.reg .b32 ra;\n\t"
        "mapa.shared::cluster.u32 ra, %0, %1;\n\t"
        "mbarrier.arrive.shared::cluster.b64 _, [ra];\n\t}"
        :: "r"(m), "r"(peer) : "memory");
}
__device__ __forceinline__ void mbar_expect_tx(uint32_t m, uint32_t bytes) {
    asm volatile("mbarrier.arrive.expect_tx.shared::cta.b64 _, [%0], %1;"
                 :: "r"(m), "r"(bytes) : "memory");
}
__device__ __forceinline__ void bulk_mcast(uint32_t dst, const void* src,
                                           uint32_t bytes, uint32_t mbar,
                                           uint16_t mask) {
    asm volatile(
        "cp.async.bulk.shared::cluster.global.mbarrier::complete_tx::bytes"
        ".multicast::cluster [%0], [%1], %2, [%3], %4;"
        :: "r"(dst), "l"(src), "r"(bytes), "r"(mbar), "h"(mask) : "memory");
}

__global__ void __cluster_dims__(2, 1, 1) __launch_bounds__(THREADS, 1)
rnn_sample_kernel(const float* __restrict__ Wx,
                  const float* __restrict__ Wh,
                  const float* __restrict__ bias,
                  const float* __restrict__ Dw,
                  const float* __restrict__ Db,
                  float* __restrict__ out)
{
    extern __shared__ __align__(16) char smem_raw[];
    float* wring = reinterpret_cast<float*>(smem_raw + W_OFF);
    float* h_s   = reinterpret_cast<float*>(smem_raw + H_OFF);
    unsigned long long* red = reinterpret_cast<unsigned long long*>(smem_raw + RED_OFF);
    float* gum   = reinterpret_cast<float*>(smem_raw + GUM_OFF);
    int*   s_arr = reinterpret_cast<int*>(smem_raw + S_OFF);

    const uint32_t sb    = smem_u32(smem_raw);
    const uint32_t w_u32 = sb + W_OFF;
    const uint32_t mb    = sb + MB_OFF;          // full[s]=mb+8s, empty[s]=mb+24+8s
    const int tid  = threadIdx.x;
    const int lane = tid & 31;
    const int warp = tid >> 5;
    const int half = (tid >> 8) & 1;             // consumers: 0 -> even chunks, 1 -> odd
    const int j    = tid & 255;
    const int bbase = blockIdx.x * NB;
    const uint32_t rank = ctarank();
    const uint32_t peer = rank ^ 1u;

    // ---- one-time init ----
    for (int i = tid; i < NHID * HSTRIDE; i += THREADS) h_s[i] = 0.0f;
    for (int i = tid; i < NSITES * NB * 2; i += THREADS) {
        int t = i >> 4, r = i & 15;
        int b = r >> 1, cls = r & 1;
        uint32_t o0, o1;
        tf2x32(0u, 42u, 0u, (uint32_t)t, o0, o1);
        gum[i] = gumbel_from(rbits_part(o0, o1, (uint32_t)(2 * (bbase + b) + cls)));
    }
    if (tid < NB) s_arr[tid] = -1;
    if (tid == 0) {
        for (int s = 0; s < RING; ++s) {
            mbar_init(mb + 8 * s, 1);            // full: expect_tx arrival
            mbar_init(mb + 24 + 8 * s, 16);      // empty: 8 local + 8 peer warps
        }
    }
    float logP = 0.0f;
    __syncthreads();
    // cluster-wide: mbar init + smem visible before any multicast TMA
    asm volatile("barrier.cluster.arrive.aligned;" ::: "memory");
    asm volatile("barrier.cluster.wait.aligned;" ::: "memory");

    if (warp == NCHUNK) {                        // ---- producer warp (warp 16) ----
        if (lane == 0) {
            const char* wsrc = reinterpret_cast<const char*>(Wh);
            for (int g = 0; g < NSITES * NCHUNK; ++g) {
                int c  = g & 15;
                int q3 = g / 3;
                int s  = g - 3 * q3;
                mbar_wait(mb + 24 + 8 * s, (uint32_t)((q3 & 1) ^ 1));
                mbar_expect_tx(mb + 8 * s, CHUNK_BYTES);
                bulk_mcast(w_u32 + s * CHUNK_BYTES + rank * SLICE_BYTES,
                           wsrc + (size_t)c * CHUNK_BYTES + rank * SLICE_BYTES,
                           SLICE_BYTES, mb + 8 * s, (uint16_t)0x3);
            }
        }
    } else {                                     // ---- consumer warps 0-15 ----
        const float b0z = bias[j],     b0r = bias[256 + j],  b0n = bias[512 + j];
        const float c0z = b0z + Wx[j],      c0r = b0r + Wx[256 + j],
                    c0n = b0n + Wx[512 + j];
        const float c1z = b0z + Wx[G3 + j], c1r = b0r + Wx[G3 + 256 + j],
                    c1n = b0n + Wx[G3 + 512 + j];
        const float b1z = bias[G3 + j], b1r = bias[G3 + 256 + j],
                    b1n = bias[G3 + 512 + j];
        const float db0 = Db[0], db1 = Db[1];
        const int op = 2 * half;

        for (int i = 0; i < NSITES; ++i) {
            // ---- phase 1: consume my half's 8 chunks (even or odd) ----
            unsigned long long acc[12];
#pragma unroll
            for (int a = 0; a < 12; ++a) acc[a] = 0ull;
            for (int t8 = 0; t8 < 8; ++t8) {
                int c  = 2 * t8 + half;
                int g  = i * NCHUNK + c;
                int q3 = g / 3;
                int s  = g - 3 * q3;
                mbar_wait(mb + 8 * s, (uint32_t)(q3 & 1));
                const float* wch = wring + s * (CHUNK_BYTES / 4) + j;
                const float* hch = h_s + (c * CHUNK_K) * HSTRIDE;
#pragma unroll
                for (int k = 0; k < CHUNK_K; ++k) {
                    unsigned long long w0 = pack2(wch[k * G3]);
                    unsigned long long w1 = pack2(wch[k * G3 + 256]);
                    unsigned long long w2 = pack2(wch[k * G3 + 512]);
                    const ulonglong2* hp =
                        reinterpret_cast<const ulonglong2*>(hch + k * HSTRIDE);
                    ulonglong2 hA = hp[0], hB = hp[1];
                    fma2(acc[0], w0, hA.x); fma2(acc[1], w0, hA.y);
                    fma2(acc[2], w0, hB.x); fma2(acc[3], w0, hB.y);
                    fma2(acc[4], w1, hA.x); fma2(acc[5], w1, hA.y);
                    fma2(acc[6], w1, hB.x); fma2(acc[7], w1, hB.y);
                    fma2(acc[8], w2, hA.x); fma2(acc[9], w2, hA.y);
                    fma2(acc[10], w2, hB.x); fma2(acc[11], w2, hB.y);
                }
                __syncwarp();
                if (lane == 0) {
                    mbar_arrive(mb + 24 + 8 * s);
                    mbar_arrive_peer(mb + 24 + 8 * s, peer);
                }
            }
            // store the 6 partials the OTHER half needs: red[slot][half][j]
            {
                const int cp = 2 * (1 - half);
                red[(0 * 2 + half) * NHID + j] = acc[cp];
                red[(1 * 2 + half) * NHID + j] = acc[cp + 1];
                red[(2 * 2 + half) * NHID + j] = acc[4 + cp];
                red[(3 * 2 + half) * NHID + j] = acc[4 + cp + 1];
                red[(4 * 2 + half) * NHID + j] = acc[8 + cp];
                red[(5 * 2 + half) * NHID + j] = acc[8 + cp + 1];
            }
            // head for step i-1 (warps 0-7; h_s stable in phase 1)
            if (warp < NB && i > 0) {
                const int b = warp, t = i - 1;
                float c0 = 0.0f, c1 = 0.0f;
                for (int k = lane; k < NHID; k += 32) {
                    float hv = h_s[k * HSTRIDE + b];
                    c0 += hv * Dw[2 * k];
                    c1 += hv * Dw[2 * k + 1];
                }
#pragma unroll
                for (int off = 16; off > 0; off >>= 1) {
                    c0 += __shfl_down_sync(0xffffffffu, c0, off);
                    c1 += __shfl_down_sync(0xffffffffu, c1, off);
                }
                if (lane == 0) {
                    float la = c0 + db0, lb = c1 + db1;
                    float m  = fmaxf(la, lb);
                    float ea = expf(la - m), eb = expf(lb - m);
                    float sm = ea + eb;
                    float lp0 = logf(1e-10f + ea / sm);
                    float lp1 = logf(1e-10f + eb / sm);
                    float g0 = gum[(t * NB + b) * 2];
                    float g1 = gum[(t * NB + b) * 2 + 1];
                    int s = (g1 + lp1 > g0 + lp0) ? 1 : 0;
                    logP += s ? lp1 : lp0;
                    s_arr[b] = s;
                    out[(bbase + b) * NSITES + t] = (float)s;
                }
            }
            asm volatile("bar.sync 1, 512;" ::: "memory");   // red + s_arr ready

            // ---- phase 2: combine (evens + odds) + gates for my 4 samples ----
            {
                const int oh = 1 - half;
                unsigned long long oz0 = red[(0 * 2 + oh) * NHID + j];
                unsigned long long oz1 = red[(1 * 2 + oh) * NHID + j];
                unsigned long long or0 = red[(2 * 2 + oh) * NHID + j];
                unsigned long long or1 = red[(3 * 2 + oh) * NHID + j];
                unsigned long long on0 = red[(4 * 2 + oh) * NHID + j];
                unsigned long long on1 = red[(5 * 2 + oh) * NHID + j];
                unsigned long long sz0, sz1, sr0, sr1, sn0, sn1;
                if (half == 0) {   // own = evens
                    sz0 = add2(acc[op],     oz0); sz1 = add2(acc[op + 1],     oz1);
                    sr0 = add2(acc[4 + op], or0); sr1 = add2(acc[4 + op + 1], or1);
                    sn0 = add2(acc[8 + op], on0); sn1 = add2(acc[8 + op + 1], on1);
                } else {           // other = evens first
                    sz0 = add2(oz0, acc[op]);     sz1 = add2(oz1, acc[op + 1]);
                    sr0 = add2(or0, acc[4 + op]); sr1 = add2(or1, acc[4 + op + 1]);
                    sn0 = add2(on0, acc[8 + op]); sn1 = add2(on1, acc[8 + op + 1]);
                }
                float gz[4], gr[4], gn[4];
                unpack2(sz0, gz[0], gz[1]); unpack2(sz1, gz[2], gz[3]);
                unpack2(sr0, gr[0], gr[1]); unpack2(sr1, gr[2], gr[3]);
                unpack2(sn0, gn[0], gn[1]); unpack2(sn1, gn[2], gn[3]);

                float4 hold = *reinterpret_cast<float4*>(h_s + j * HSTRIDE + 4 * half);
                float ho[4] = {hold.x, hold.y, hold.z, hold.w};
                float hn4[4];
#pragma unroll
                for (int v = 0; v < 4; ++v) {
                    int b = 4 * half + v;
                    int sp = s_arr[b];
                    float gxz, gxr, gxn;
                    if (i == 0) { gxz = b0z; gxr = b0r; gxn = b0n; }
                    else if (sp) { gxz = c1z; gxr = c1r; gxn = c1n; }
                    else         { gxz = c0z; gxr = c0r; gxn = c0n; }
                    float z  = sigmoid_x(gxz + gz[v] + b1z);
                    float r  = sigmoid_x(gxr + gr[v] + b1r);
                    float hh = tanhf(gxn + r * (gn[v] + b1n));
                    hn4[v] = z * ho[v] + (1.0f - z) * hh;
                }
                *reinterpret_cast<float4*>(h_s + j * HSTRIDE + 4 * half) =
                    make_float4(hn4[0], hn4[1], hn4[2], hn4[3]);
            }
            asm volatile("bar.sync 1, 512;" ::: "memory");   // h ready
        }

        // ---- epilogue head: step NSITES-1 ----
        if (warp < NB) {
            const int b = warp, t = NSITES - 1;
            float c0 = 0.0f, c1 = 0.0f;
            for (int k = lane; k < NHID; k += 32) {
                float hv = h_s[k * HSTRIDE + b];
                c0 += hv * Dw[2 * k];
                c1 += hv * Dw[2 * k + 1];
            }
#pragma unroll
            for (int off = 16; off > 0; off >>= 1) {
                c0 += __shfl_down_sync(0xffffffffu, c0, off);
                c1 += __shfl_down_sync(0xffffffffu, c1, off);
            }
            if (lane == 0) {
                float la = c0 + db0, lb = c1 + db1;
                float m  = fmaxf(la, lb);
                float ea = expf(la - m), eb = expf(lb - m);
                float sm = ea + eb;
                float lp0 = logf(1e-10f + ea / sm);
                float lp1 = logf(1e-10f + eb / sm);
                float g0 = gum[(t * NB + b) * 2];
                float g1 = gum[(t * NB + b) * 2 + 1];
                int s = (g1 + lp1 > g0 + lp0) ? 1 : 0;
                logP += s ? lp1 : lp0;
                out[(bbase + b) * NSITES + t] = (float)s;
                out[BATCH * NSITES + bbase + b] = logP;
            }
        }
    }

    // cluster-wide exit barrier: no CTA leaves while peer ops may target its smem
    asm volatile("barrier.cluster.arrive.aligned;" ::: "memory");
    asm volatile("barrier.cluster.wait.aligned;" ::: "memory");
}

extern "C" void kernel_launch(void* const* d_in, const int* in_sizes, int n_in,
                              void* d_out, int out_size) {
    (void)in_sizes; (void)n_in; (void)out_size;
    const float* Wx   = (const float*)d_in[0];
    const float* Wh   = (const float*)d_in[1];
    const float* bias = (const float*)d_in[2];
    const float* Dw   = (const float*)d_in[3];
    const float* Db   = (const float*)d_in[4];
    float* out = (float*)d_out;
    cudaFuncSetAttribute(rnn_sample_kernel,
                         cudaFuncAttributeMaxDynamicSharedMemorySize, SMEM_TOTAL);
    rnn_sample_kernel<<<NBLOCKS, THREADS, SMEM_TOTAL>>>(Wx, Wh, bias, Dw, Db, out);
}